// round 3
// baseline (speedup 1.0000x reference)
#include <cuda_runtime.h>
#include <cstdint>

// Problem constants (match reference)
#define V_VARS 256
#define N_PER_VAR 16
#define C_CATS 256
#define B_BATCH 4096
#define NUM_NODES (V_VARS * N_PER_VAR)

__device__ __forceinline__ float eval_one(float p, int m, float a) {
    // out = mask ? 0 : log(max(p,1e-10)*a + (1-a))
    float arg = fmaxf(p, 1e-10f) * a + (1.0f - a);
    float r = __logf(arg);
    return m ? 0.0f : r;
}

__global__ __launch_bounds__(256, 4)
void categorical_kernel(
    const int* __restrict__ data,      // [V, B] int32, values in [0, C)
    const int* __restrict__ vids,      // [NUM_NODES] int32
    const int* __restrict__ psids,     // [NUM_NODES] int32
    const float* __restrict__ params,  // [NUM_NODES * C]
    const int* __restrict__ mask,      // [V, B] bool -> int32
    const float* __restrict__ alphas,  // [V, B]
    float* __restrict__ out)           // [NUM_NODES, B]
{
    const int n = blockIdx.x;
    const int v = vids[n];
    const int ps = psids[n];

    const float* __restrict__ prow = params + ps;
    const int* __restrict__ drow = data + v * B_BATCH;
    const int* __restrict__ mrow = mask + v * B_BATCH;
    const float* __restrict__ arow = alphas + v * B_BATCH;
    float* __restrict__ orow = out + (long long)n * B_BATCH;

    const int t4 = threadIdx.x * 4;

    #pragma unroll
    for (int it = 0; it < B_BATCH / (256 * 4); ++it) {
        const int b = it * (256 * 4) + t4;

        int4   d4 = *reinterpret_cast<const int4*>(drow + b);
        int4   m4 = *reinterpret_cast<const int4*>(mrow + b);
        float4 a4 = *reinterpret_cast<const float4*>(arow + b);

        float p0 = prow[d4.x];
        float p1 = prow[d4.y];
        float p2 = prow[d4.z];
        float p3 = prow[d4.w];

        float4 r;
        r.x = eval_one(p0, m4.x, a4.x);
        r.y = eval_one(p1, m4.y, a4.y);
        r.z = eval_one(p2, m4.z, a4.z);
        r.w = eval_one(p3, m4.w, a4.w);

        *reinterpret_cast<float4*>(orow + b) = r;
    }
}

extern "C" void kernel_launch(void* const* d_in, const int* in_sizes, int n_in,
                              void* d_out, int out_size) {
    const int* data     = (const int*)d_in[0];
    const int* vids     = (const int*)d_in[1];
    const int* psids    = (const int*)d_in[2];
    const float* params = (const float*)d_in[3];
    const int* mm       = (const int*)d_in[4];
    const float* alphas = (const float*)d_in[5];
    float* out          = (float*)d_out;

    categorical_kernel<<<NUM_NODES, 256>>>(data, vids, psids, params, mm, alphas, out);
}

// round 4
// speedup vs baseline: 1.3266x; 1.3266x over previous
#include <cuda_runtime.h>
#include <cstdint>

#define V_VARS 256
#define N_PER_VAR 16
#define C_CATS 256
#define B_BATCH 4096
#define NUM_NODES (V_VARS * N_PER_VAR)
#define NCHUNKS 4
#define BCHUNK (B_BATCH / NCHUNKS)   // 1024 = 256 threads * 4

__global__ __launch_bounds__(256, 4)
void categorical_kernel(
    const int* __restrict__ data,      // [V, B] int32
    const int* __restrict__ vids,      // [NUM_NODES] int32
    const int* __restrict__ psids,     // [NUM_NODES] int32
    const float* __restrict__ params,  // [NUM_NODES * C]
    const int* __restrict__ mask,      // [V, B] bool -> int32
    const float* __restrict__ alphas,  // [V, B]
    float* __restrict__ out)           // [NUM_NODES, B]
{
    __shared__ float sp[N_PER_VAR][C_CATS];   // 16 KB

    const int tid   = threadIdx.x;
    const int vblk  = blockIdx.x >> 2;        // variable group index (0..255)
    const int chunk = blockIdx.x & (NCHUNKS - 1);
    const int n0    = vblk * N_PER_VAR;       // first node of this variable
    const int v     = vids[n0];               // == vblk by construction, but honor input

    // Stage the 16 param rows (1 KB each) into shared. 256 threads = 1 row/iter.
    #pragma unroll
    for (int c = 0; c < N_PER_VAR; ++c) {
        const int ps = psids[n0 + c];
        sp[c][tid] = params[ps + tid];
    }
    __syncthreads();

    const int b = chunk * BCHUNK + tid * 4;

    const int*   __restrict__ drow = data   + v * B_BATCH;
    const int*   __restrict__ mrow = mask   + v * B_BATCH;
    const float* __restrict__ arow = alphas + v * B_BATCH;

    // One vector read of evidence serves all 16 nodes.
    int4   d4 = *reinterpret_cast<const int4*>(drow + b);
    int4   m4 = *reinterpret_cast<const int4*>(mrow + b);
    float4 a4 = *reinterpret_cast<const float4*>(arow + b);

    const float c0 = 1.0f - a4.x;
    const float c1 = 1.0f - a4.y;
    const float c2 = 1.0f - a4.z;
    const float c3 = 1.0f - a4.w;

    float* orow = out + (long long)n0 * B_BATCH + b;

    #pragma unroll
    for (int c = 0; c < N_PER_VAR; ++c) {
        float p0 = sp[c][d4.x];
        float p1 = sp[c][d4.y];
        float p2 = sp[c][d4.z];
        float p3 = sp[c][d4.w];

        float4 r;
        r.x = m4.x ? 0.0f : __logf(fmaxf(p0, 1e-10f) * a4.x + c0);
        r.y = m4.y ? 0.0f : __logf(fmaxf(p1, 1e-10f) * a4.y + c1);
        r.z = m4.z ? 0.0f : __logf(fmaxf(p2, 1e-10f) * a4.z + c2);
        r.w = m4.w ? 0.0f : __logf(fmaxf(p3, 1e-10f) * a4.w + c3);

        *reinterpret_cast<float4*>(orow) = r;
        orow += B_BATCH;   // next node's row
    }
}

extern "C" void kernel_launch(void* const* d_in, const int* in_sizes, int n_in,
                              void* d_out, int out_size) {
    const int* data     = (const int*)d_in[0];
    const int* vids     = (const int*)d_in[1];
    const int* psids    = (const int*)d_in[2];
    const float* params = (const float*)d_in[3];
    const int* mm       = (const int*)d_in[4];
    const float* alphas = (const float*)d_in[5];
    float* out          = (float*)d_out;

    categorical_kernel<<<V_VARS * NCHUNKS, 256>>>(data, vids, psids, params, mm, alphas, out);
}